// round 1
// baseline (speedup 1.0000x reference)
#include <cuda_runtime.h>
#include <cuda_bf16.h>
#include <stdint.h>

// LengthRegulator: B=32, S=1024, E=256
//   cum = cumsum(duration, axis=1); mel_len = cum[:, -1]; max_mel = max(mel_len)
//   out[b, t, :] = x[b, searchsorted(cum[b], t, 'right'), :]   for t <  mel_len[b]
//   out[b, t, :] = 0,  mask[b, t] = 1                          for t >= mel_len[b]
// Output buffer layout (derived from out_size on host):
//   [ out (B*max_mel*E floats) | mask (B*max_mel floats) ]  if has_mask

#define BB 32
#define SS 1024
#define EE 256

// Scratch (no allocations allowed): per-batch inclusive cumsum + totals.
__device__ int g_cum[BB * SS];
__device__ int g_mel[BB];

// ---------------------------------------------------------------------------
// Kernel 1: per-batch inclusive scan of duration. One block per batch.
// Detects on-device whether `duration` is int64 (jax x64 on) or int32
// (jax default downcasts the reference's astype(int64)).
// int64 LE => every odd 32-bit word is the zero high-half.
// ---------------------------------------------------------------------------
__global__ void lr_scan_kernel(const void* __restrict__ dur_raw) {
    __shared__ int warp_sums[32];
    __shared__ int s_is64;

    const int b   = blockIdx.x;
    const int tid = threadIdx.x;

    if (tid == 0) {
        const unsigned* w = (const unsigned*)dur_raw;
        unsigned acc = 0;
        #pragma unroll
        for (int i = 1; i < 256; i += 2) acc |= w[i];  // 128 odd words
        s_is64 = (acc == 0u) ? 1 : 0;
    }
    __syncthreads();

    int v;
    if (s_is64) {
        v = (int)((const long long*)dur_raw)[b * SS + tid];
    } else {
        v = ((const int*)dur_raw)[b * SS + tid];
    }

    // warp-level inclusive scan
    const int lane = tid & 31;
    const int wid  = tid >> 5;
    int sv = v;
    #pragma unroll
    for (int o = 1; o < 32; o <<= 1) {
        int n = __shfl_up_sync(0xffffffffu, sv, o);
        if (lane >= o) sv += n;
    }
    if (lane == 31) warp_sums[wid] = sv;
    __syncthreads();

    if (wid == 0) {
        int ws = warp_sums[lane];
        #pragma unroll
        for (int o = 1; o < 32; o <<= 1) {
            int n = __shfl_up_sync(0xffffffffu, ws, o);
            if (lane >= o) ws += n;
        }
        warp_sums[lane] = ws;
    }
    __syncthreads();

    const int incl = sv + (wid > 0 ? warp_sums[wid - 1] : 0);
    g_cum[b * SS + tid] = incl;
    if (tid == SS - 1) g_mel[b] = incl;
}

// ---------------------------------------------------------------------------
// Kernel 2: expand. One warp per output row (b, t).
//   t <  mel_len[b]: binary-search cum row, copy 256 floats (float4 x2/lane)
//   t >= mel_len[b]: zero-fill row
// Mask written as float 0/1 by lane 0 (output buffer dtype is float32).
// ---------------------------------------------------------------------------
__global__ void lr_expand_kernel(const float* __restrict__ x,
                                 float* __restrict__ out,
                                 int max_mel, int has_mask) {
    const int warp = (blockIdx.x * blockDim.x + threadIdx.x) >> 5;
    const int lane = threadIdx.x & 31;
    const int total_rows = BB * max_mel;
    if (warp >= total_rows) return;

    const int b = warp / max_mel;
    const int t = warp - b * max_mel;
    const int L = g_mel[b];

    float4 v0, v1;
    if (t < L) {
        // searchsorted(cum, t, 'right'): first s with cum[s] > t. Since
        // t < L = cum[S-1], result <= S-1 (reference's min(idx, S-1) is a no-op).
        const int* __restrict__ c = &g_cum[b * SS];
        int lo = 0, hi = SS;
        while (lo < hi) {
            int mid = (lo + hi) >> 1;
            if (c[mid] <= t) lo = mid + 1; else hi = mid;
        }
        const float4* __restrict__ xr =
            (const float4*)(x + ((size_t)b * SS + (size_t)lo) * EE);
        v0 = xr[lane];
        v1 = xr[lane + 32];
    } else {
        v0 = make_float4(0.f, 0.f, 0.f, 0.f);
        v1 = v0;
    }

    float4* __restrict__ orow = (float4*)(out + (size_t)warp * EE);
    orow[lane]      = v0;
    orow[lane + 32] = v1;

    if (has_mask && lane == 0) {
        out[(size_t)total_rows * EE + warp] = (t >= L) ? 1.0f : 0.0f;
    }
}

// ---------------------------------------------------------------------------
extern "C" void kernel_launch(void* const* d_in, const int* in_sizes, int n_in,
                              void* d_out, int out_size) {
    (void)in_sizes; (void)n_in;
    const float* x   = (const float*)d_in[0];
    const void*  dur = d_in[1];
    float* out = (float*)d_out;

    // Derive max_mel and layout from out_size (data-dependent, fixed per run).
    // Tuple-concatenated layout: B*max_mel*(E+1); out-only: B*max_mel*E.
    int has_mask, max_mel;
    if (out_size % (BB * (EE + 1)) == 0) {
        has_mask = 1;
        max_mel  = out_size / (BB * (EE + 1));
    } else {
        has_mask = 0;
        max_mel  = out_size / (BB * EE);
    }

    lr_scan_kernel<<<BB, SS>>>(dur);

    const int total_rows = BB * max_mel;          // one warp per row
    const int threads = 256;                      // 8 warps / block
    const int blocks  = (total_rows + 7) / 8;
    lr_expand_kernel<<<blocks, threads>>>(x, out, max_mel, has_mask);
}

// round 3
// speedup vs baseline: 1.7288x; 1.7288x over previous
#include <cuda_runtime.h>
#include <cuda_bf16.h>
#include <stdint.h>

// LengthRegulator: B=32, S=1024, E=256
//   cum = cumsum(duration, axis=1); mel_len = cum[:, -1]; max_mel = max(mel_len)
//   out[b, t, :] = x[b, idx(b,t), :]  where idx = searchsorted(cum[b], t, 'right')
//   tail rows (t >= mel_len[b]) are zero; mask[b,t] = (t >= mel_len[b]) ? 1 : 0
// Output buffer: [ out (B*max_mel*E f32) | mask (B*max_mel f32) ] if has_mask.
//
// R1 redesign: scan kernel INVERTS the searchsorted by scattering s into an
// index table (duration <= 7 writes/thread), so the expand kernel does a single
// uniform idx load per row instead of a 10-deep dependent binary search.

#define BB 32
#define SS 1024
#define EE 256
#define MAXM_PAD 7168   // max possible mel length = 7 * 1024

__device__ int g_idx[BB * MAXM_PAD];  // source row per output row
__device__ int g_mel[BB];             // mel_len per batch

// ---------------------------------------------------------------------------
// Kernel 1: per-batch inclusive scan of duration + scatter inverse index.
// One block per batch, 1024 threads. Handles int64 or int32 duration
// (int64 LE => all odd 32-bit words are zero high-halves; dur values 0..7).
// ---------------------------------------------------------------------------
__global__ void lr_scan_kernel(const void* __restrict__ dur_raw) {
    __shared__ int warp_sums[32];
    __shared__ int s_is64;

    const int b   = blockIdx.x;
    const int tid = threadIdx.x;

    if (tid == 0) {
        const unsigned* w = (const unsigned*)dur_raw;
        unsigned acc = 0;
        #pragma unroll
        for (int i = 1; i < 256; i += 2) acc |= w[i];  // 128 odd words
        s_is64 = (acc == 0u) ? 1 : 0;
    }
    __syncthreads();

    int v;
    if (s_is64) {
        v = (int)((const long long*)dur_raw)[b * SS + tid];
    } else {
        v = ((const int*)dur_raw)[b * SS + tid];
    }

    // warp inclusive scan
    const int lane = tid & 31;
    const int wid  = tid >> 5;
    int sv = v;
    #pragma unroll
    for (int o = 1; o < 32; o <<= 1) {
        int n = __shfl_up_sync(0xffffffffu, sv, o);
        if (lane >= o) sv += n;
    }
    if (lane == 31) warp_sums[wid] = sv;
    __syncthreads();

    if (wid == 0) {
        int ws = warp_sums[lane];
        #pragma unroll
        for (int o = 1; o < 32; o <<= 1) {
            int n = __shfl_up_sync(0xffffffffu, ws, o);
            if (lane >= o) ws += n;
        }
        warp_sums[lane] = ws;
    }
    __syncthreads();

    const int incl = sv + (wid > 0 ? warp_sums[wid - 1] : 0);
    const int excl = incl - v;

    // scatter: output rows [excl, incl) come from source row tid
    int* __restrict__ row = &g_idx[b * MAXM_PAD];
    for (int t = excl; t < incl; ++t) row[t] = tid;

    if (tid == SS - 1) g_mel[b] = incl;
}

// ---------------------------------------------------------------------------
// Kernel 2: expand. One warp per output row. grid = (ceil(max_mel/WPB), B).
// Single uniform idx load (L1-broadcast), then 2x float4 load + 2x streaming
// float4 store per lane. Tail rows zero-filled; mask float written by lane 0.
// ---------------------------------------------------------------------------
#define WPB 8   // warps per block

__global__ void lr_expand_kernel(const float* __restrict__ x,
                                 float* __restrict__ out,
                                 int max_mel, int has_mask) {
    const int b    = blockIdx.y;
    const int t    = blockIdx.x * WPB + (threadIdx.x >> 5);
    const int lane = threadIdx.x & 31;
    if (t >= max_mel) return;

    const int L = g_mel[b];

    float4 v0 = make_float4(0.f, 0.f, 0.f, 0.f);
    float4 v1 = v0;
    if (t < L) {
        const int s = g_idx[b * MAXM_PAD + t];
        const float4* __restrict__ xr =
            (const float4*)(x + ((size_t)b * SS + (size_t)s) * EE);
        v0 = __ldg(&xr[lane]);
        v1 = __ldg(&xr[lane + 32]);
    }

    const size_t row = (size_t)b * max_mel + t;
    float4* __restrict__ orow = (float4*)(out + row * EE);
    __stcs(&orow[lane],      v0);   // streaming: don't thrash L2 with 122MB of
    __stcs(&orow[lane + 32], v1);   // write-once output

    if (has_mask && lane == 0) {
        out[(size_t)BB * max_mel * EE + row] = (t >= L) ? 1.0f : 0.0f;
    }
}

// ---------------------------------------------------------------------------
extern "C" void kernel_launch(void* const* d_in, const int* in_sizes, int n_in,
                              void* d_out, int out_size) {
    (void)in_sizes; (void)n_in;
    const float* x   = (const float*)d_in[0];
    const void*  dur = d_in[1];
    float* out = (float*)d_out;

    // Derive max_mel / layout from out_size (fixed per run).
    int has_mask, max_mel;
    if (out_size % (BB * (EE + 1)) == 0) {
        has_mask = 1;
        max_mel  = out_size / (BB * (EE + 1));
    } else {
        has_mask = 0;
        max_mel  = out_size / (BB * EE);
    }

    lr_scan_kernel<<<BB, SS>>>(dur);

    dim3 grid((max_mel + WPB - 1) / WPB, BB);
    lr_expand_kernel<<<grid, WPB * 32>>>(x, out, max_mel, has_mask);
}